// round 11
// baseline (speedup 1.0000x reference)
#include <cuda_runtime.h>
#include <cstdint>

#define BB     8
#define NWAY   10
#define KSHOT  5
#define QN     500
#define DD     768
#define NQ     (BB * QN)        // 4000
#define NL     (NWAY + 1)       // 11
#define TILEQ  32               // queries per block
#define TPE    16               // tiles per episode (15 full + 1 with 20)
#define NBLK   (BB * TPE)       // 128 blocks
#define TPB    512              // 16 warps: warp w = D-chunk w*48 floats
#define SQ4    (DD / 4)         // 192 f4 per row
#define QSTR   193              // padded f4 stride for q rows (odd -> conflict-free)
#define DCH    12               // f4 per D-chunk (48 floats)
#define REDW   13               // padded width of reduction rows (odd)

__device__ float g_S[BB * NWAY * DD];
__device__ float g_ssq[BB * NWAY];

struct __align__(16) F4p { unsigned long long u0, u1; };

__device__ __forceinline__ void ffma2(unsigned long long& d,
                                      unsigned long long a,
                                      unsigned long long b) {
    asm("fma.rn.f32x2 %0, %1, %2, %0;" : "+l"(d) : "l"(a), "l"(b));
}
__device__ __forceinline__ float pair_sum(unsigned long long u) {
    float lo, hi;
    asm("mov.b64 {%0, %1}, %2;" : "=f"(lo), "=f"(hi) : "l"(u));
    return lo + hi;
}
__device__ __forceinline__ uint32_t smem_u32(const void* p) {
    uint32_t a;
    asm("{ .reg .u64 t; cvta.to.shared.u64 t, %1; cvt.u32.u64 %0, t; }"
        : "=r"(a) : "l"(p));
    return a;
}
__device__ __forceinline__ void cp16(uint32_t dst, const void* src) {
    asm volatile("cp.async.cg.shared.global [%0], [%1], 16;"
                 :: "r"(dst), "l"(src) : "memory");
}
#define CP_COMMIT()  asm volatile("cp.async.commit_group;" ::: "memory")
#define CP_WAIT0()   asm volatile("cp.async.wait_group 0;"  ::: "memory")

// ---------------------------------------------------------------------------
// Kernel 1: prototypes + squared norms. One block per (b,n).
// ---------------------------------------------------------------------------
__global__ void __launch_bounds__(128) proto_kernel(const float* __restrict__ sup) {
    int bn = blockIdx.x;
    int t  = threadIdx.x;
    const float* base = sup + (size_t)bn * KSHOT * DD;
    float part = 0.0f;
#pragma unroll
    for (int j = 0; j < DD / 128; j++) {
        int d = t + j * 128;
        float s = 0.0f;
#pragma unroll
        for (int k = 0; k < KSHOT; k++) s += base[k * DD + d];
        s *= 0.2f;
        g_S[bn * DD + d] = s;
        part += s * s;
    }
#pragma unroll
    for (int off = 16; off; off >>= 1)
        part += __shfl_xor_sync(0xffffffffu, part, off);
    __shared__ float red[4];
    if ((t & 31) == 0) red[t >> 5] = part;
    __syncthreads();
    if (t == 0) g_ssq[bn] = red[0] + red[1] + red[2] + red[3];
}

// ---------------------------------------------------------------------------
// Kernel 2: transposed dataflow. Block = 32-query tile; warp w = D-chunk;
// lane l = query l. q lane-specific (padded stride), S broadcast (16B/bank-op).
// No warp shuffles; cross-warp reduce via smem.
// ---------------------------------------------------------------------------
__global__ void __launch_bounds__(TPB, 1) main_kernel(const float* __restrict__ qin,
                                                      float* __restrict__ out,
                                                      int out_size) {
    extern __shared__ char smraw[];
    float4* sQ   = (float4*)smraw;                         // 32*193 f4 = 98816 B
    float4* sS   = sQ + TILEQ * QSTR;                      // 1920 f4  = 30720 B
    float*  red  = (float*)(sS + NWAY * SQ4);              // 16*32*13 = 26624 B
    float*  redr = red + 16 * TILEQ * REDW;                // 32*13    = 1664 B

    int tid  = threadIdx.x;
    int lane = tid & 31;
    int wid  = tid >> 5;                    // 0..15 : D-chunk index
    int ep   = blockIdx.x >> 4;             // episode
    int tile = blockIdx.x & 15;             // tile within episode
    int rows = (tile < TPE - 1) ? TILEQ : (QN - (TPE - 1) * TILEQ);  // 32 or 20

    // prefetch ssq early (consumed by warp 0 in the epilogue)
    float ssq_r = (lane < NWAY) ? g_ssq[ep * NWAY + lane] : 0.0f;

    // ---- async fills: Q tile (6144 f4) + S (1920 f4), one commit group ----
    {
        const float4* __restrict__ gq =
            (const float4*)qin + ((size_t)ep * QN + tile * TILEQ) * SQ4;
        uint32_t dq = smem_u32(sQ);
#pragma unroll
        for (int i = 0; i < 12; i++) {
            int idx = tid + i * TPB;        // < 6144
            int r   = idx / SQ4;
            int c   = idx - r * SQ4;
            int rs  = (r < rows) ? r : 0;   // clamp OOB rows of last tile
            cp16(dq + (r * QSTR + c) * 16, gq + rs * SQ4 + c);
        }
        const float4* __restrict__ gs = (const float4*)(g_S + (size_t)ep * NWAY * DD);
        uint32_t ds = smem_u32(sS);
#pragma unroll
        for (int i = 0; i < 4; i++) {
            int idx = tid + i * TPB;
            if (idx < NWAY * SQ4) cp16(ds + idx * 16, gs + idx);
        }
    }
    CP_COMMIT();
    CP_WAIT0();
    __syncthreads();

    // ---- compute: lane l = query l, warp wid = D floats [wid*48, wid*48+48) --
    unsigned long long acc2[NWAY];
#pragma unroll
    for (int n = 0; n < NWAY; n++) acc2[n] = 0ull;
    unsigned long long qs2 = 0ull;

    int d0 = wid * DCH;
#pragma unroll
    for (int j = 0; j < DCH; j++) {
        F4p q = *(const F4p*)&sQ[lane * QSTR + d0 + j];    // conflict-free
        ffma2(qs2, q.u0, q.u0);
        ffma2(qs2, q.u1, q.u1);
#pragma unroll
        for (int n = 0; n < NWAY; n++) {
            F4p s = *(const F4p*)&sS[n * SQ4 + d0 + j];    // broadcast
            ffma2(acc2[n], s.u0, q.u0);
            ffma2(acc2[n], s.u1, q.u1);
        }
    }

    // ---- stage partials: red[wid][lane][k], k=0..9 dots, k=10 qsq ----
    {
        float* rp = red + (wid * TILEQ + lane) * REDW;     // stride 13: no conflicts
#pragma unroll
        for (int n = 0; n < NWAY; n++) rp[n] = pair_sum(acc2[n]);
        rp[NWAY] = pair_sum(qs2);
    }
    __syncthreads();

    // ---- cross-warp reduce: 352 threads, one (q,k) each, 16-way sum ----
    if (tid < TILEQ * NL) {
        int q = tid / NL;
        int k = tid - q * NL;
        float s = 0.0f;
#pragma unroll
        for (int w = 0; w < 16; w++)
            s += red[(w * TILEQ + q) * REDW + k];
        redr[q * REDW + k] = s;
    }
    __syncthreads();

    // ---- epilogue: warp 0, lane = query ----
    if (wid == 0) {
        int q_ep = tile * TILEQ + lane;
        int qq   = ep * QN + q_ep;
        bool valid = (lane < rows);

        float dot[NWAY], qsq;
#pragma unroll
        for (int n = 0; n < NWAY; n++) dot[n] = redr[lane * REDW + n];
        qsq = redr[lane * REDW + NWAY];

        float lg[NL];
        float mn =  3.4e38f, mx = -3.4e38f;
#pragma unroll
        for (int n = 0; n < NWAY; n++) {
            float sn = __shfl_sync(0xffffffffu, ssq_r, n);
            float v  = 2.0f * dot[n] - sn - qsq;
            lg[n] = v;
            mn = fminf(mn, v);
            mx = fmaxf(mx, v);
        }
        lg[NWAY] = mn - 1.0f;

        float ex[NL];
        float se = 0.0f;
#pragma unroll
        for (int i = 0; i < NL; i++) {
            ex[i] = __expf(lg[i] - mx);
            se += ex[i];
        }
        float inv = 1.0f / se;

        int   amax = 0;
        float bv   = lg[0];
#pragma unroll
        for (int n = 1; n < NWAY; n++)
            if (lg[n] > bv) { bv = lg[n]; amax = n; }

        if (valid) {
            // Output layout: fh[NQ*NL] | ph[NQ*NL] | yh_top[NQ] | ph_top[NQ]
            float* fh = out + (size_t)qq * NL;
#pragma unroll
            for (int i = 0; i < NL; i++) fh[i] = lg[i];

            if (out_size >= 2 * NQ * NL) {
                float* ph = out + (size_t)NQ * NL + (size_t)qq * NL;
#pragma unroll
                for (int i = 0; i < NL; i++) ph[i] = ex[i] * inv;
            }
            if (out_size >= 2 * NQ * NL + NQ)
                out[2 * NQ * NL + qq] = (float)amax;
            if (out_size >= 2 * NQ * NL + 2 * NQ)
                out[2 * NQ * NL + NQ + qq] = inv;   // max softmax = e^0 * inv
        }
    }
}

extern "C" void kernel_launch(void* const* d_in, const int* in_sizes, int n_in,
                              void* d_out, int out_size) {
    const float* support = (const float*)d_in[0];
    const float* query   = (const float*)d_in[1];
    float* out = (float*)d_out;

    const int smem_bytes = TILEQ * QSTR * 16 + NWAY * SQ4 * 16
                         + 16 * TILEQ * REDW * 4 + TILEQ * REDW * 4;  // ~157.8 KB
    static bool configured = false;
    if (!configured) {
        cudaFuncSetAttribute(main_kernel,
                             cudaFuncAttributeMaxDynamicSharedMemorySize,
                             smem_bytes);
        configured = true;
    }

    proto_kernel<<<BB * NWAY, 128>>>(support);
    main_kernel<<<NBLK, TPB, smem_bytes>>>(query, out, out_size);
}

// round 12
// speedup vs baseline: 1.1596x; 1.1596x over previous
#include <cuda_runtime.h>
#include <cstdint>

#define BB     8
#define NWAY   10
#define KSHOT  5
#define QN     500
#define DD     768
#define NQ     (BB * QN)        // 4000
#define NL     (NWAY + 1)       // 11
#define QPW    2                // queries per warp
#define BLKW   4                // warps per block (128 threads)
#define QPB    (QPW * BLKW)     // 8 queries per block
#define BPE    63               // blocks per episode (62 full + 1 half)
#define NBLK   (BB * BPE)       // 504
#define SQ4    (DD / 4)         // 192 float4 per row
#define SFILL  (NWAY * SQ4)     // 1920 float4
#define QFILL  (QPB * SQ4)      // 1536 float4

__device__ float g_S[BB * NWAY * DD];
__device__ float g_ssq[BB * NWAY];

struct __align__(16) F4p { unsigned long long u0, u1; };

__device__ __forceinline__ void ffma2(unsigned long long& d,
                                      unsigned long long a,
                                      unsigned long long b) {
    asm("fma.rn.f32x2 %0, %1, %2, %0;" : "+l"(d) : "l"(a), "l"(b));
}
__device__ __forceinline__ float pair_sum(unsigned long long u) {
    float lo, hi;
    asm("mov.b64 {%0, %1}, %2;" : "=f"(lo), "=f"(hi) : "l"(u));
    return lo + hi;
}
__device__ __forceinline__ float fold(float a, float b, int off, int lane) {
    float oa = __shfl_xor_sync(0xffffffffu, a, off);
    float ob = __shfl_xor_sync(0xffffffffu, b, off);
    return (lane & off) ? (b + ob) : (a + oa);
}
__device__ __forceinline__ int base_lane(int n) {
    return n < 8 ? (((n & 1) << 3) | ((n & 2) << 1) | ((n & 4) >> 1))
                 : (((n & 1) << 3) | 1);
}
__device__ __forceinline__ uint32_t smem_u32(const void* p) {
    uint32_t a;
    asm("{ .reg .u64 t; cvta.to.shared.u64 t, %1; cvt.u32.u64 %0, t; }"
        : "=r"(a) : "l"(p));
    return a;
}
__device__ __forceinline__ void cp16(uint32_t dst, const void* src) {
    asm volatile("cp.async.cg.shared.global [%0], [%1], 16;"
                 :: "r"(dst), "l"(src) : "memory");
}
#define CP_COMMIT()  asm volatile("cp.async.commit_group;" ::: "memory")
#define CP_WAIT0()   asm volatile("cp.async.wait_group 0;"  ::: "memory")

// ---------------------------------------------------------------------------
// Kernel 1: prototypes + squared norms. One block per (b,n).
// ---------------------------------------------------------------------------
__global__ void __launch_bounds__(128) proto_kernel(const float* __restrict__ sup) {
    int bn = blockIdx.x;
    int t  = threadIdx.x;
    const float* base = sup + (size_t)bn * KSHOT * DD;
    float part = 0.0f;
#pragma unroll
    for (int j = 0; j < DD / 128; j++) {
        int d = t + j * 128;
        float s = 0.0f;
#pragma unroll
        for (int k = 0; k < KSHOT; k++) s += base[k * DD + d];
        s *= 0.2f;
        g_S[bn * DD + d] = s;
        part += s * s;
    }
#pragma unroll
    for (int off = 16; off; off >>= 1)
        part += __shfl_xor_sync(0xffffffffu, part, off);
    __shared__ float red[4];
    if ((t & 31) == 0) red[t >> 5] = part;
    __syncthreads();
    if (t == 0) g_ssq[bn] = red[0] + red[1] + red[2] + red[3];
    cudaTriggerProgrammaticLaunchCompletion();
}

// ---------------------------------------------------------------------------
// Kernel 2 (PDL dependent): starts its query cp.async stream IMMEDIATELY
// (independent of proto), then grid-dependency-syncs before touching g_S /
// g_ssq. Proto's whole execution hides under the 12.3 MB query fetch.
// ---------------------------------------------------------------------------
__global__ void __launch_bounds__(128, 4) main_kernel(const float* __restrict__ qin,
                                                      float* __restrict__ out,
                                                      int out_size) {
    extern __shared__ float4 smem[];
    float4* sS = smem;                       // [SFILL]  30 KB
    float4* sQ = smem + SFILL;               // [QFILL]  24 KB

    int tid   = threadIdx.x;
    int lane  = tid & 31;
    int wwarp = tid >> 5;
    int b     = blockIdx.x / BPE;
    int blk   = blockIdx.x - b * BPE;

    int  qin_ep = blk * QPB + wwarp * QPW;
    bool active = (qin_ep < QN);             // QN even: pair fully valid

    // ---- async Q fill FIRST (does not depend on proto output) ----
    {
        const float4* __restrict__ gq =
            (const float4*)(qin + (size_t)b * QN * DD) + (size_t)blk * QPB * SQ4;
        uint32_t d0 = smem_u32(sQ);
        int rem_rows = QN - blk * QPB;       // rows still in this episode
#pragma unroll
        for (int i = 0; i < 12; i++) {
            int idx  = tid + i * 128;
            int src  = (idx / SQ4 < rem_rows) ? idx : (idx % SQ4); // clamp OOB
            cp16(d0 + idx * 16, gq + src);
        }
    }
    CP_COMMIT();

    // ---- wait for proto grid completion, THEN read its outputs ----
    cudaGridDependencySynchronize();

    float ssq_r = (lane < NWAY) ? g_ssq[b * NWAY + lane] : 0.0f;

    // ---- async S fill: 1920 float4 / 128 threads = 15 cp.async each ----
    {
        const float4* __restrict__ gs = (const float4*)(g_S + (size_t)b * NWAY * DD);
        uint32_t d0 = smem_u32(sS);
#pragma unroll
        for (int i = 0; i < 15; i++) {
            int idx = tid + i * 128;
            cp16(d0 + idx * 16, gs + idx);
        }
    }
    CP_COMMIT();
    CP_WAIT0();                              // waits both groups
    __syncthreads();
    if (!active) return;

    // ---- lift q into registers (12 LDS.128) ----
    F4p qp[QPW][6];
#pragma unroll
    for (int qi = 0; qi < QPW; qi++)
#pragma unroll
        for (int j = 0; j < 6; j++)
            qp[qi][j] = *(const F4p*)&sQ[(wwarp * QPW + qi) * SQ4 + lane + 32 * j];

    // ---- packed accumulation: 60 LDS.128 + 240 FFMA2 per warp ----
    unsigned long long acc2[QPW][NWAY];
#pragma unroll
    for (int qi = 0; qi < QPW; qi++)
#pragma unroll
        for (int n = 0; n < NWAY; n++) acc2[qi][n] = 0ull;

    unsigned long long qs2[QPW] = {0ull, 0ull};
#pragma unroll
    for (int qi = 0; qi < QPW; qi++)
#pragma unroll
        for (int j = 0; j < 6; j++) {
            ffma2(qs2[qi], qp[qi][j].u0, qp[qi][j].u0);
            ffma2(qs2[qi], qp[qi][j].u1, qp[qi][j].u1);
        }

#pragma unroll
    for (int j = 0; j < 6; j++) {
#pragma unroll
        for (int n = 0; n < NWAY; n++) {
            F4p s = *(const F4p*)&sS[n * SQ4 + lane + 32 * j];
#pragma unroll
            for (int qi = 0; qi < QPW; qi++) {
                ffma2(acc2[qi][n], s.u0, qp[qi][j].u0);
                ffma2(acc2[qi][n], s.u1, qp[qi][j].u1);
            }
        }
    }

    // ---- 22 scalars -> folded butterfly ----
    float v[22];
#pragma unroll
    for (int n = 0; n < NWAY; n++) {
        v[2 * n]     = pair_sum(acc2[0][n]);
        v[2 * n + 1] = pair_sum(acc2[1][n]);
    }
    v[20] = pair_sum(qs2[0]);
    v[21] = pair_sum(qs2[1]);

    float a0 = fold(v[0],  v[1],  16, lane);
    float a1 = fold(v[2],  v[3],  16, lane);
    float a2 = fold(v[4],  v[5],  16, lane);
    float a3 = fold(v[6],  v[7],  16, lane);
    float a4 = fold(v[8],  v[9],  16, lane);
    float a5 = fold(v[10], v[11], 16, lane);
    float a6 = fold(v[12], v[13], 16, lane);
    float a7 = fold(v[14], v[15], 16, lane);
    float a8 = fold(v[16], v[17], 16, lane);
    float a9 = fold(v[18], v[19], 16, lane);
    float a10 = fold(v[20], v[21], 16, lane);

    float b0 = fold(a0, a1, 8, lane);
    float b1 = fold(a2, a3, 8, lane);
    float b2 = fold(a4, a5, 8, lane);
    float b3 = fold(a6, a7, 8, lane);
    float b4 = fold(a8, a9, 8, lane);
    float b5 = a10 + __shfl_xor_sync(0xffffffffu, a10, 8);

    float c0 = fold(b0, b1, 4, lane);
    float c1 = fold(b2, b3, 4, lane);
    float c2 = fold(b4, b5, 4, lane);

    float d0 = fold(c0, c1, 2, lane);
    float d1 = c2 + __shfl_xor_sync(0xffffffffu, c2, 2);

    float e = fold(d0, d1, 1, lane);
    // dot(qi,n) at lane base_lane(n)+16*qi; qsq(qi) at lane 5+16*qi.

    // ---- per-half-warp epilogue ----
    int qhalf = lane >> 4;
    int c     = lane & 15;
    int qq    = b * QN + qin_ep + qhalf;
    int lsel  = qhalf << 4;

    float qsqv = __shfl_sync(0xffffffffu, e, 5 + lsel);

    float lg[NWAY];
    float my_lg = 0.0f;
    float mn =  3.4e38f, mx = -3.4e38f;
#pragma unroll
    for (int n = 0; n < NWAY; n++) {
        float dv = __shfl_sync(0xffffffffu, e, base_lane(n) + lsel);
        float sn = __shfl_sync(0xffffffffu, ssq_r, n);
        float w  = 2.0f * dv - sn - qsqv;
        lg[n] = w;
        mn = fminf(mn, w);
        mx = fmaxf(mx, w);
        if (c == n) my_lg = w;
    }
    float lg10 = mn - 1.0f;
    if (c == 10) my_lg = lg10;

    float se = __expf(lg10 - mx);
#pragma unroll
    for (int n = 0; n < NWAY; n++) se += __expf(lg[n] - mx);
    float inv = 1.0f / se;

    int   amax = 0;
    float bv   = lg[0];
#pragma unroll
    for (int n = 1; n < NWAY; n++)
        if (lg[n] > bv) { bv = lg[n]; amax = n; }

    // Output layout: fh[NQ*NL] | ph[NQ*NL] | yh_top[NQ] | ph_top[NQ]
    if (c < NL) {
        out[(size_t)qq * NL + c] = my_lg;
        if (out_size >= 2 * NQ * NL)
            out[(size_t)NQ * NL + (size_t)qq * NL + c] = __expf(my_lg - mx) * inv;
    }
    if (c == 0) {
        if (out_size >= 2 * NQ * NL + NQ)
            out[2 * NQ * NL + qq] = (float)amax;
        if (out_size >= 2 * NQ * NL + 2 * NQ)
            out[2 * NQ * NL + NQ + qq] = inv;   // ph_top = e^0 * inv
    }
}

extern "C" void kernel_launch(void* const* d_in, const int* in_sizes, int n_in,
                              void* d_out, int out_size) {
    const float* support = (const float*)d_in[0];
    const float* query   = (const float*)d_in[1];
    float* out = (float*)d_out;

    const int smem_bytes = (SFILL + QFILL) * 16;   // 55296 B
    static bool configured = false;
    if (!configured) {
        cudaFuncSetAttribute(main_kernel,
                             cudaFuncAttributeMaxDynamicSharedMemorySize,
                             smem_bytes);
        configured = true;
    }

    proto_kernel<<<BB * NWAY, 128>>>(support);

    // Dependent launch: main starts while proto runs; its gridDepSync
    // provides the ordering for g_S / g_ssq.
    cudaLaunchConfig_t cfg = {};
    cfg.gridDim          = dim3(NBLK, 1, 1);
    cfg.blockDim         = dim3(128, 1, 1);
    cfg.dynamicSmemBytes = smem_bytes;
    cfg.stream           = 0;
    cudaLaunchAttribute attr[1];
    attr[0].id = cudaLaunchAttributeProgrammaticStreamSerialization;
    attr[0].val.programmaticStreamSerializationAllowed = 1;
    cfg.attrs    = attr;
    cfg.numAttrs = 1;
    cudaLaunchKernelEx(&cfg, main_kernel, query, out, out_size);
}